// round 10
// baseline (speedup 1.0000x reference)
#include <cuda_runtime.h>

// FuzzyARTMAP single fused kernel: match scores + row sums + argmax.
// N=1024, D=256, C=512, fp32. match[n,c] = sum_d min(x,w) / sum_d x; gate 0.75;
// first-occurrence argmax.
//
// R10: whole-D resident tiles. As/Bs hold the full 64x256 strips (133KB dynamic
// smem, 1 block/SM), loaded once with one __syncthreads(), then 256 k-steps of
// uninterrupted 4x4 math with ZERO barriers — removing the per-BK-tile barrier
// phases that synchronized all warps to the slowest (the measured ~2x overhead
// that occupancy/ILP/instruction-count changes could never fix).

#define N_ROWS 1024
#define D_DIM  256
#define C_CATS 512
#define VIG    0.75f

#define BM 64
#define BN 64
#define NCB (C_CATS / BN)     // column-blocks per row = 8
#define LSTRIDE 260           // 1040B row stride == 16B mod 128B: conflict-free LDS.128

__device__ unsigned long long g_key[N_ROWS];   // zero at load; self-reset each launch
__device__ unsigned int       g_cnt[N_ROWS];   // zero at load; self-reset each launch

static const int SMEM_BYTES = 2 * BM * LSTRIDE * 4;   // 133120 B

// ---------------------------------------------------------------------------
__global__ __launch_bounds__(256) void fused_kernel(const float* __restrict__ x,
                                                    const float* __restrict__ w,
                                                    float* __restrict__ out,
                                                    float* __restrict__ idx_out) {
    extern __shared__ float smem[];
    float* As = smem;                      // [BM][LSTRIDE] x strip
    float* Bs = smem + BM * LSTRIDE;       // [BN][LSTRIDE] w strip
    __shared__ float xq[BM][4];                   // per-row quarter sums of x
    __shared__ unsigned long long skey[BM];       // per-row best (val, col) key

    const int t  = threadIdx.x;
    const int tx = t & 15;        // 16 thread-columns
    const int ty = t >> 4;        // 16 thread-rows (4 rows each)
    const int rowBase = blockIdx.y * BM;
    const int colBase = blockIdx.x * BN;

    if (t < BM) skey[t] = 0ull;

    // ---- Single bulk load of the whole 64x256 strips (32 LDG.128 per thread) ----
    const int lr = t >> 4;        // row group 0..15
    const int lc = t & 15;        // float4 col 0..15
    #pragma unroll
    for (int i = 0; i < 4; i++) {
        int r = lr + 16 * i;
        const float* xr = x + (size_t)(rowBase + r) * D_DIM;
        const float* wr = w + (size_t)(colBase + r) * D_DIM;
        float* ar = As + r * LSTRIDE;
        float* br = Bs + r * LSTRIDE;
        #pragma unroll
        for (int j = 0; j < 4; j++) {
            int c4 = lc + 16 * j;
            *(float4*)(ar + 4 * c4) = *(const float4*)(xr + 4 * c4);
            *(float4*)(br + 4 * c4) = *(const float4*)(wr + 4 * c4);
        }
    }
    __syncthreads();               // the ONLY pre-epilogue barrier

    // ---- Fused x row sums: 4 threads per row, 64 contiguous elems each ----
    {
        const int xr_ = t >> 2;
        const int xc_ = (t & 3) * 64;
        const float* rp = As + xr_ * LSTRIDE + xc_;
        float s = 0.f;
        #pragma unroll
        for (int u = 0; u < 16; u++) {
            float4 v = *(const float4*)(rp + 4 * u);
            s += (v.x + v.y) + (v.z + v.w);
        }
        xq[xr_][t & 3] = s;
    }

    // ---- 256 uninterrupted k-steps of 4x4 min-plus ----
    float acc[4][4];
    #pragma unroll
    for (int i = 0; i < 4; i++)
        #pragma unroll
        for (int j = 0; j < 4; j++) acc[i][j] = 0.f;

    const float* a0p = As + (4 * ty + 0) * LSTRIDE;
    const float* a1p = As + (4 * ty + 1) * LSTRIDE;
    const float* a2p = As + (4 * ty + 2) * LSTRIDE;
    const float* a3p = As + (4 * ty + 3) * LSTRIDE;
    const float* b0p = Bs + (tx +  0) * LSTRIDE;
    const float* b1p = Bs + (tx + 16) * LSTRIDE;
    const float* b2p = Bs + (tx + 32) * LSTRIDE;
    const float* b3p = Bs + (tx + 48) * LSTRIDE;

    #pragma unroll 4
    for (int k = 0; k < D_DIM; k += 4) {
        float4 a0 = *(const float4*)(a0p + k);
        float4 a1 = *(const float4*)(a1p + k);
        float4 a2 = *(const float4*)(a2p + k);
        float4 a3 = *(const float4*)(a3p + k);
        float4 b0 = *(const float4*)(b0p + k);
        float4 b1 = *(const float4*)(b1p + k);
        float4 b2 = *(const float4*)(b2p + k);
        float4 b3 = *(const float4*)(b3p + k);

        #define STEP(F)                                \
            acc[0][0] += fminf(a0.F, b0.F);           \
            acc[0][1] += fminf(a0.F, b1.F);           \
            acc[0][2] += fminf(a0.F, b2.F);           \
            acc[0][3] += fminf(a0.F, b3.F);           \
            acc[1][0] += fminf(a1.F, b0.F);           \
            acc[1][1] += fminf(a1.F, b1.F);           \
            acc[1][2] += fminf(a1.F, b2.F);           \
            acc[1][3] += fminf(a1.F, b3.F);           \
            acc[2][0] += fminf(a2.F, b0.F);           \
            acc[2][1] += fminf(a2.F, b1.F);           \
            acc[2][2] += fminf(a2.F, b2.F);           \
            acc[2][3] += fminf(a2.F, b3.F);           \
            acc[3][0] += fminf(a3.F, b0.F);           \
            acc[3][1] += fminf(a3.F, b1.F);           \
            acc[3][2] += fminf(a3.F, b2.F);           \
            acc[3][3] += fminf(a3.F, b3.F);
        STEP(x) STEP(y) STEP(z) STEP(w)
        #undef STEP
    }
    __syncthreads();               // xq visibility for the epilogue

    // ---- Epilogue: divide, gate, store, per-row argmax key ----
    #pragma unroll
    for (int i = 0; i < 4; i++) {
        int r = 4 * ty + i;
        int n = rowBase + r;
        float xs = (xq[r][0] + xq[r][1]) + (xq[r][2] + xq[r][3]);
        unsigned long long bk = 0ull;
        #pragma unroll
        for (int j = 0; j < 4; j++) {
            int c = colBase + tx + 16 * j;
            float m = acc[i][j] / xs;                  // exact division, as reference
            float g = (m >= VIG) ? m : 0.f;
            out[(size_t)n * C_CATS + c] = g;
            // order-preserving key: larger value wins; ties -> smaller column
            unsigned long long key =
                ((unsigned long long)__float_as_uint(g) << 32) |
                (unsigned long long)(unsigned)(C_CATS - 1 - c);
            if (key > bk) bk = key;
        }
        atomicMax(&skey[r], bk);
    }
    __syncthreads();

    // ---- Cross-block argmax finalization (threadfence reduction, 8 col-blocks) ----
    if (t < BM) {
        int n = rowBase + t;
        atomicMax(&g_key[n], skey[t]);
        __threadfence();
        unsigned old = atomicAdd(&g_cnt[n], 1u);
        if (old == NCB - 1) {                              // last column-block for this row
            __threadfence();
            unsigned long long k = atomicMax(&g_key[n], 0ull);   // atomic read
            if (idx_out)
                idx_out[n] = (float)(C_CATS - 1 - (unsigned)(k & 0xffffffffull));
            g_key[n] = 0ull;                               // self-clean for next replay
            g_cnt[n] = 0u;
        }
    }
}

// ---------------------------------------------------------------------------
extern "C" void kernel_launch(void* const* d_in, const int* in_sizes, int n_in,
                              void* d_out, int out_size) {
    const float* x = (const float*)d_in[0];
    const float* w = (const float*)d_in[1];
    float* out = (float*)d_out;

    static int smem_set = 0;
    if (!smem_set) {
        cudaFuncSetAttribute(fused_kernel,
                             cudaFuncAttributeMaxDynamicSharedMemorySize, SMEM_BYTES);
        smem_set = 1;
    }

    float* idx_out = (out_size >= N_ROWS * C_CATS + N_ROWS)
                   ? out + (size_t)N_ROWS * C_CATS : nullptr;

    dim3 grid(C_CATS / BN, N_ROWS / BM);   // (8, 16) = 128 blocks
    fused_kernel<<<grid, 256, SMEM_BYTES>>>(x, w, out, idx_out);
}

// round 11
// speedup vs baseline: 1.3542x; 1.3542x over previous
#include <cuda_runtime.h>

// FuzzyARTMAP single fused kernel: match scores + row sums + argmax.
// N=1024, D=256, C=512, fp32. match[n,c] = sum_d min(x,w) / sum_d x; gate 0.75;
// first-occurrence argmax.
//
// R11: byte-exact reassembly of the measured-fastest core (R3: 256 threads, 4x4
// micro-tile, scalar inner LDS, LSTRIDE=65, BK=64, NO prefetch, regs ~59) plus
// only the two proven fusions: in-loop x row-sums and in-kernel argmax
// finalization. Everything disproved in R4-R10 (prefetch, f32x2, split-K,
// barrier removal, occupancy scaling) is deliberately absent.

#define N_ROWS 1024
#define D_DIM  256
#define C_CATS 512
#define VIG    0.75f

#define BM 64
#define BN 64
#define BK 64
#define NCB (C_CATS / BN)     // column-blocks per row = 8
#define LSTRIDE 65            // R3's stride: conflict-free for scalar column access

__device__ unsigned long long g_key[N_ROWS];   // zero at load; self-reset each launch
__device__ unsigned int       g_cnt[N_ROWS];   // zero at load; self-reset each launch

// ---------------------------------------------------------------------------
__global__ __launch_bounds__(256) void fused_kernel(const float* __restrict__ x,
                                                    const float* __restrict__ w,
                                                    float* __restrict__ out,
                                                    float* __restrict__ idx_out) {
    __shared__ float As[BM][LSTRIDE];             // x tile [m][k]
    __shared__ float Bs[BN][LSTRIDE];             // w tile [c][k]
    __shared__ float xq[BM][4];                   // per-row quarter sums of x
    __shared__ unsigned long long skey[BM];       // per-row best (val, col) key

    const int t  = threadIdx.x;
    const int tx = t & 15;
    const int ty = t >> 4;
    const int rowBase = blockIdx.y * BM;
    const int colBase = blockIdx.x * BN;

    // tile-load mapping: 4 float4 per array per thread (exactly as R3)
    const int lr = t >> 4;   // 0..15
    const int lc = t & 15;   // float4 column index (BK/4 = 16)

    float acc[4][4];
    #pragma unroll
    for (int i = 0; i < 4; i++)
        #pragma unroll
        for (int j = 0; j < 4; j++) acc[i][j] = 0.f;

    float xpart = 0.f;                 // x row-sum duty: 4 threads/row, 16 elems each
    const int xr = t >> 2;
    const int xc = (t & 3) * 16;

    if (t < BM) skey[t] = 0ull;

    for (int k0 = 0; k0 < D_DIM; k0 += BK) {
        #pragma unroll
        for (int i = 0; i < 4; i++) {
            int r = lr + 16 * i;
            float4 v = *(const float4*)(x + (size_t)(rowBase + r) * D_DIM + k0 + 4 * lc);
            As[r][4 * lc + 0] = v.x;
            As[r][4 * lc + 1] = v.y;
            As[r][4 * lc + 2] = v.z;
            As[r][4 * lc + 3] = v.w;
        }
        #pragma unroll
        for (int i = 0; i < 4; i++) {
            int r = lr + 16 * i;
            float4 v = *(const float4*)(w + (size_t)(colBase + r) * D_DIM + k0 + 4 * lc);
            Bs[r][4 * lc + 0] = v.x;
            Bs[r][4 * lc + 1] = v.y;
            Bs[r][4 * lc + 2] = v.z;
            Bs[r][4 * lc + 3] = v.w;
        }
        __syncthreads();

        // fused xsum: each thread sums a 16-wide quarter of one As row (scalar LDS;
        // rows are not 16B-aligned at stride 65).
        {
            const float* rp = &As[xr][xc];
            float s = 0.f;
            #pragma unroll
            for (int u = 0; u < 16; u++) s += rp[u];
            xpart += s;
        }

        #pragma unroll 16
        for (int k = 0; k < BK; k++) {
            float a0 = As[4 * ty + 0][k];
            float a1 = As[4 * ty + 1][k];
            float a2 = As[4 * ty + 2][k];
            float a3 = As[4 * ty + 3][k];
            float b0 = Bs[tx +  0][k];
            float b1 = Bs[tx + 16][k];
            float b2 = Bs[tx + 32][k];
            float b3 = Bs[tx + 48][k];

            acc[0][0] += fminf(a0, b0); acc[0][1] += fminf(a0, b1);
            acc[0][2] += fminf(a0, b2); acc[0][3] += fminf(a0, b3);
            acc[1][0] += fminf(a1, b0); acc[1][1] += fminf(a1, b1);
            acc[1][2] += fminf(a1, b2); acc[1][3] += fminf(a1, b3);
            acc[2][0] += fminf(a2, b0); acc[2][1] += fminf(a2, b1);
            acc[2][2] += fminf(a2, b2); acc[2][3] += fminf(a2, b3);
            acc[3][0] += fminf(a3, b0); acc[3][1] += fminf(a3, b1);
            acc[3][2] += fminf(a3, b2); acc[3][3] += fminf(a3, b3);
        }
        __syncthreads();
    }

    xq[xr][t & 3] = xpart;
    __syncthreads();

    // Epilogue: divide, gate, store, per-row argmax key.
    #pragma unroll
    for (int i = 0; i < 4; i++) {
        int r = 4 * ty + i;
        int n = rowBase + r;
        float xs = (xq[r][0] + xq[r][1]) + (xq[r][2] + xq[r][3]);
        unsigned long long bk = 0ull;
        #pragma unroll
        for (int j = 0; j < 4; j++) {
            int c = colBase + tx + 16 * j;
            float m = acc[i][j] / xs;                  // exact division, as reference
            float g = (m >= VIG) ? m : 0.f;
            out[(size_t)n * C_CATS + c] = g;
            // order-preserving key: larger value wins; ties -> smaller column
            unsigned long long key =
                ((unsigned long long)__float_as_uint(g) << 32) |
                (unsigned long long)(unsigned)(C_CATS - 1 - c);
            if (key > bk) bk = key;
        }
        atomicMax(&skey[r], bk);
    }
    __syncthreads();

    // Cross-block argmax finalization (threadfence reduction over 8 col-blocks).
    if (t < BM) {
        int n = rowBase + t;
        atomicMax(&g_key[n], skey[t]);
        __threadfence();
        unsigned old = atomicAdd(&g_cnt[n], 1u);
        if (old == NCB - 1) {                              // last column-block for this row
            __threadfence();
            unsigned long long k = atomicMax(&g_key[n], 0ull);   // atomic read
            if (idx_out)
                idx_out[n] = (float)(C_CATS - 1 - (unsigned)(k & 0xffffffffull));
            g_key[n] = 0ull;                               // self-clean for next replay
            g_cnt[n] = 0u;
        }
    }
}

// ---------------------------------------------------------------------------
extern "C" void kernel_launch(void* const* d_in, const int* in_sizes, int n_in,
                              void* d_out, int out_size) {
    const float* x = (const float*)d_in[0];
    const float* w = (const float*)d_in[1];
    float* out = (float*)d_out;

    float* idx_out = (out_size >= N_ROWS * C_CATS + N_ROWS)
                   ? out + (size_t)N_ROWS * C_CATS : nullptr;

    dim3 grid(C_CATS / BN, N_ROWS / BM);   // (8, 16) = 128 blocks
    fused_kernel<<<grid, 256>>>(x, w, out, idx_out);
}

// round 12
// speedup vs baseline: 1.4684x; 1.0843x over previous
#include <cuda_runtime.h>

// FuzzyARTMAP single fused kernel: match scores + row sums + argmax.
// N=1024, D=256, C=512, fp32. match[n,c] = sum_d min(x,w) / sum_d x; gate 0.75;
// first-occurrence argmax.
//
// R12: break the low-grid issue-throttle (+28% @ grid<148 with body>32KB, vanishes
// @ grid>=148 — B300_MICROARCH I-cache section). BM=32 x BN=64 tiles -> 256 blocks
// (>=148, all SMs engaged, single wave at 2 blocks/SM), and the inner loop is kept
// small (#pragma unroll 4, ~5KB body, fits L0 I$) instead of fully unrolled.
// 2x4 micro-tile, 256 threads, fused x row-sums + in-kernel argmax finalization.

#define N_ROWS 1024
#define D_DIM  256
#define C_CATS 512
#define VIG    0.75f

#define BM 32
#define BN 64
#define BK 64
#define NCB (C_CATS / BN)     // column-blocks per row = 8
#define LSTRIDE 68            // 16B-aligned rows, conflict-free LDS.128

__device__ unsigned long long g_key[N_ROWS];   // zero at load; self-reset each launch
__device__ unsigned int       g_cnt[N_ROWS];   // zero at load; self-reset each launch

// ---------------------------------------------------------------------------
__global__ __launch_bounds__(256) void fused_kernel(const float* __restrict__ x,
                                                    const float* __restrict__ w,
                                                    float* __restrict__ out,
                                                    float* __restrict__ idx_out) {
    __shared__ float As[BM][LSTRIDE];             // x tile [m][k]  (32 rows)
    __shared__ float Bs[BN][LSTRIDE];             // w tile [c][k]  (64 rows)
    __shared__ float xq[BM][8];                   // per-row 1/8 sums of x
    __shared__ unsigned long long skey[BM];       // per-row best (val, col) key

    const int t  = threadIdx.x;
    const int tx = t & 15;        // 16 thread-columns (4 cols each, stride 16)
    const int ty = t >> 4;        // 16 thread-rows (2 rows each)
    const int rowBase = blockIdx.y * BM;
    const int colBase = blockIdx.x * BN;

    float acc[2][4];
    #pragma unroll
    for (int i = 0; i < 2; i++)
        #pragma unroll
        for (int j = 0; j < 4; j++) acc[i][j] = 0.f;

    float xpart = 0.f;             // x row-sum duty: 8 threads per row, 8 elems each
    const int xr = t >> 3;         // 0..31
    const int xc = (t & 7) * 8;

    if (t < BM) skey[t] = 0ull;

    for (int k0 = 0; k0 < D_DIM; k0 += BK) {
        // As: 32x64 = 512 float4, 2 per thread. Bs: 64x64 = 1024 float4, 4 per thread.
        #pragma unroll
        for (int i = 0; i < 2; i++) {
            int idx = t + 256 * i;
            int r   = idx >> 4;
            int c4  = idx & 15;
            *(float4*)&As[r][4 * c4] =
                *(const float4*)(x + (size_t)(rowBase + r) * D_DIM + k0 + 4 * c4);
        }
        #pragma unroll
        for (int i = 0; i < 4; i++) {
            int idx = t + 256 * i;
            int r   = idx >> 4;
            int c4  = idx & 15;
            *(float4*)&Bs[r][4 * c4] =
                *(const float4*)(w + (size_t)(colBase + r) * D_DIM + k0 + 4 * c4);
        }
        __syncthreads();

        // Fused row-sum: each thread sums an 8-wide slice of one As row.
        {
            float4 v0 = *(const float4*)&As[xr][xc];
            float4 v1 = *(const float4*)&As[xr][xc + 4];
            xpart += (v0.x + v0.y) + (v0.z + v0.w) + (v1.x + v1.y) + (v1.z + v1.w);
        }

        // Small body: 4 chunks of 4 k each per iteration (~5KB SASS, fits L0 I$).
        #pragma unroll 4
        for (int k = 0; k < BK; k += 4) {
            float4 a0 = *(const float4*)&As[2 * ty + 0][k];
            float4 a1 = *(const float4*)&As[2 * ty + 1][k];
            float4 b0 = *(const float4*)&Bs[tx +  0][k];
            float4 b1 = *(const float4*)&Bs[tx + 16][k];
            float4 b2 = *(const float4*)&Bs[tx + 32][k];
            float4 b3 = *(const float4*)&Bs[tx + 48][k];

            #define STEP(F)                                \
                acc[0][0] += fminf(a0.F, b0.F);           \
                acc[0][1] += fminf(a0.F, b1.F);           \
                acc[0][2] += fminf(a0.F, b2.F);           \
                acc[0][3] += fminf(a0.F, b3.F);           \
                acc[1][0] += fminf(a1.F, b0.F);           \
                acc[1][1] += fminf(a1.F, b1.F);           \
                acc[1][2] += fminf(a1.F, b2.F);           \
                acc[1][3] += fminf(a1.F, b3.F);
            STEP(x) STEP(y) STEP(z) STEP(w)
            #undef STEP
        }
        __syncthreads();
    }

    xq[xr][t & 7] = xpart;
    __syncthreads();

    // Epilogue: divide, gate, store, per-row argmax key.
    #pragma unroll
    for (int i = 0; i < 2; i++) {
        int r = 2 * ty + i;
        int n = rowBase + r;
        float xs = ((xq[r][0] + xq[r][1]) + (xq[r][2] + xq[r][3]))
                 + ((xq[r][4] + xq[r][5]) + (xq[r][6] + xq[r][7]));
        unsigned long long bk = 0ull;
        #pragma unroll
        for (int j = 0; j < 4; j++) {
            int c = colBase + tx + 16 * j;
            float m = acc[i][j] / xs;                  // exact division, as reference
            float g = (m >= VIG) ? m : 0.f;
            out[(size_t)n * C_CATS + c] = g;
            // order-preserving key: larger value wins; ties -> smaller column
            unsigned long long key =
                ((unsigned long long)__float_as_uint(g) << 32) |
                (unsigned long long)(unsigned)(C_CATS - 1 - c);
            if (key > bk) bk = key;
        }
        atomicMax(&skey[r], bk);
    }
    __syncthreads();

    // Cross-block argmax finalization (threadfence reduction over 8 col-blocks).
    if (t < BM) {
        int n = rowBase + t;
        atomicMax(&g_key[n], skey[t]);
        __threadfence();
        unsigned old = atomicAdd(&g_cnt[n], 1u);
        if (old == NCB - 1) {                              // last column-block for this row
            __threadfence();
            unsigned long long k = atomicMax(&g_key[n], 0ull);   // atomic read
            if (idx_out)
                idx_out[n] = (float)(C_CATS - 1 - (unsigned)(k & 0xffffffffull));
            g_key[n] = 0ull;                               // self-clean for next replay
            g_cnt[n] = 0u;
        }
    }
}

// ---------------------------------------------------------------------------
extern "C" void kernel_launch(void* const* d_in, const int* in_sizes, int n_in,
                              void* d_out, int out_size) {
    const float* x = (const float*)d_in[0];
    const float* w = (const float*)d_in[1];
    float* out = (float*)d_out;

    float* idx_out = (out_size >= N_ROWS * C_CATS + N_ROWS)
                   ? out + (size_t)N_ROWS * C_CATS : nullptr;

    dim3 grid(C_CATS / BN, N_ROWS / BM);   // (8, 32) = 256 blocks >= 148
    fused_kernel<<<grid, 256>>>(x, w, out, idx_out);
}

// round 13
// speedup vs baseline: 1.4863x; 1.0122x over previous
#include <cuda_runtime.h>

// FuzzyARTMAP single fused kernel: match scores + row sums + argmax.
// N=1024, D=256, C=512, fp32. match[n,c] = sum_d min(x,w) / sum_d x; gate 0.75;
// first-occurrence argmax.
//
// R13: R8's measured-best core (256 thr, 4x4 micro-tile, float4 LDS, BM=BN=BK=64)
// with the LDG register-prefetch REMOVED (R8's one unvetted ingredient; it held
// +55 live registers through the math). Small unrolled body (L0 I$-resident),
// fused x row-sums, in-kernel argmax finalization. Ledger-driven excision round.

#define N_ROWS 1024
#define D_DIM  256
#define C_CATS 512
#define VIG    0.75f

#define BM 64
#define BN 64
#define BK 64
#define NCB (C_CATS / BN)     // column-blocks per row = 8
#define LSTRIDE 68            // 16B-aligned rows; conflict-free LDS.128 phases

__device__ unsigned long long g_key[N_ROWS];   // zero at load; self-reset each launch
__device__ unsigned int       g_cnt[N_ROWS];   // zero at load; self-reset each launch

// ---------------------------------------------------------------------------
__global__ __launch_bounds__(256) void fused_kernel(const float* __restrict__ x,
                                                    const float* __restrict__ w,
                                                    float* __restrict__ out,
                                                    float* __restrict__ idx_out) {
    __shared__ float As[BM][LSTRIDE];             // x tile [m][k]
    __shared__ float Bs[BN][LSTRIDE];             // w tile [c][k]
    __shared__ float xq[BM][4];                   // per-row quarter sums of x
    __shared__ unsigned long long skey[BM];       // per-row best (val, col) key

    const int t  = threadIdx.x;
    const int tx = t & 15;        // 16 thread-columns
    const int ty = t >> 4;        // 16 thread-rows (4 rows each)
    const int rowBase = blockIdx.y * BM;
    const int colBase = blockIdx.x * BN;

    float acc[4][4];
    #pragma unroll
    for (int i = 0; i < 4; i++)
        #pragma unroll
        for (int j = 0; j < 4; j++) acc[i][j] = 0.f;

    float xpart = 0.f;             // x row-sum duty: 4 threads per row, 16 elems each
    const int xr = t >> 2;
    const int xc = (t & 3) * 16;

    if (t < BM) skey[t] = 0ull;

    // Tile-load mapping: 4 float4 per array per thread (rows lr+16i).
    const int lr = t >> 4;        // 0..15
    const int lc = t & 15;        // float4 column (BK/4 = 16)

    for (int k0 = 0; k0 < D_DIM; k0 += BK) {
        // Direct LDG -> STS (no register prefetch: keeps live regs low).
        #pragma unroll
        for (int i = 0; i < 4; i++) {
            int r = lr + 16 * i;
            *(float4*)&As[r][4 * lc] =
                *(const float4*)(x + (size_t)(rowBase + r) * D_DIM + k0 + 4 * lc);
            *(float4*)&Bs[r][4 * lc] =
                *(const float4*)(w + (size_t)(colBase + r) * D_DIM + k0 + 4 * lc);
        }
        __syncthreads();

        // Fused row-sum: each thread sums a 16-wide quarter of one As row.
        {
            const float* rp = &As[xr][xc];
            float s = 0.f;
            #pragma unroll
            for (int u = 0; u < 4; u++) {
                float4 v = *(const float4*)(rp + 4 * u);
                s += (v.x + v.y) + (v.z + v.w);
            }
            xpart += s;
        }

        // Small body: unroll 4 chunks of 4k (fits L0 I$).
        #pragma unroll 4
        for (int k = 0; k < BK; k += 4) {
            float4 a0 = *(const float4*)&As[4 * ty + 0][k];
            float4 a1 = *(const float4*)&As[4 * ty + 1][k];
            float4 a2 = *(const float4*)&As[4 * ty + 2][k];
            float4 a3 = *(const float4*)&As[4 * ty + 3][k];
            float4 b0 = *(const float4*)&Bs[tx +  0][k];
            float4 b1 = *(const float4*)&Bs[tx + 16][k];
            float4 b2 = *(const float4*)&Bs[tx + 32][k];
            float4 b3 = *(const float4*)&Bs[tx + 48][k];

            #define STEP(F)                                \
                acc[0][0] += fminf(a0.F, b0.F);           \
                acc[0][1] += fminf(a0.F, b1.F);           \
                acc[0][2] += fminf(a0.F, b2.F);           \
                acc[0][3] += fminf(a0.F, b3.F);           \
                acc[1][0] += fminf(a1.F, b0.F);           \
                acc[1][1] += fminf(a1.F, b1.F);           \
                acc[1][2] += fminf(a1.F, b2.F);           \
                acc[1][3] += fminf(a1.F, b3.F);           \
                acc[2][0] += fminf(a2.F, b0.F);           \
                acc[2][1] += fminf(a2.F, b1.F);           \
                acc[2][2] += fminf(a2.F, b2.F);           \
                acc[2][3] += fminf(a2.F, b3.F);           \
                acc[3][0] += fminf(a3.F, b0.F);           \
                acc[3][1] += fminf(a3.F, b1.F);           \
                acc[3][2] += fminf(a3.F, b2.F);           \
                acc[3][3] += fminf(a3.F, b3.F);
            STEP(x) STEP(y) STEP(z) STEP(w)
            #undef STEP
        }
        __syncthreads();
    }

    xq[xr][t & 3] = xpart;
    __syncthreads();

    // Epilogue: divide, gate, store, per-row argmax key.
    #pragma unroll
    for (int i = 0; i < 4; i++) {
        int r = 4 * ty + i;
        int n = rowBase + r;
        float xs = (xq[r][0] + xq[r][1]) + (xq[r][2] + xq[r][3]);
        unsigned long long bk = 0ull;
        #pragma unroll
        for (int j = 0; j < 4; j++) {
            int c = colBase + tx + 16 * j;
            float m = acc[i][j] / xs;                  // exact division, as reference
            float g = (m >= VIG) ? m : 0.f;
            out[(size_t)n * C_CATS + c] = g;
            // order-preserving key: larger value wins; ties -> smaller column
            unsigned long long key =
                ((unsigned long long)__float_as_uint(g) << 32) |
                (unsigned long long)(unsigned)(C_CATS - 1 - c);
            if (key > bk) bk = key;
        }
        atomicMax(&skey[r], bk);
    }
    __syncthreads();

    // Cross-block argmax finalization (threadfence reduction over 8 col-blocks).
    if (t < BM) {
        int n = rowBase + t;
        atomicMax(&g_key[n], skey[t]);
        __threadfence();
        unsigned old = atomicAdd(&g_cnt[n], 1u);
        if (old == NCB - 1) {                              // last column-block for this row
            __threadfence();
            unsigned long long k = atomicMax(&g_key[n], 0ull);   // atomic read
            if (idx_out)
                idx_out[n] = (float)(C_CATS - 1 - (unsigned)(k & 0xffffffffull));
            g_key[n] = 0ull;                               // self-clean for next replay
            g_cnt[n] = 0u;
        }
    }
}

// ---------------------------------------------------------------------------
extern "C" void kernel_launch(void* const* d_in, const int* in_sizes, int n_in,
                              void* d_out, int out_size) {
    const float* x = (const float*)d_in[0];
    const float* w = (const float*)d_in[1];
    float* out = (float*)d_out;

    float* idx_out = (out_size >= N_ROWS * C_CATS + N_ROWS)
                   ? out + (size_t)N_ROWS * C_CATS : nullptr;

    dim3 grid(C_CATS / BN, N_ROWS / BM);   // (8, 16) = 128 blocks
    fused_kernel<<<grid, 256>>>(x, w, out, idx_out);
}